// round 1
// baseline (speedup 1.0000x reference)
#include <cuda_runtime.h>
#include <math.h>

#define NTOK 4096
#define CDIM 256
#define QKD  64
#define NB   4
#define PAD  132

typedef unsigned long long u64;

// ---------------- scratch (device globals; no runtime allocation) ----------------
__device__ float g_q [(size_t)NB * QKD  * NTOK];            // [b][d][i]
__device__ float g_k [(size_t)NB * QKD  * NTOK];            // [b][d][j]
__device__ float g_v [(size_t)NB * CDIM * NTOK];            // [b][c][j]
__device__ float g_S [(size_t)NB * NTOK * NTOK];            // [b][i][j] -> exp'd in place
__device__ float g_Dp[NB * 8 * NTOK];                       // partial column sums
__device__ float g_w [NB * NTOK];                           // 1 / colsum
__device__ float g_ao[(size_t)NB * NTOK * CDIM];            // attention out [b][i][c]
__device__ float g_h [(size_t)NB * CDIM * NTOK];            // hidden [b][o][i]

// ---------------- helpers ----------------
__device__ __forceinline__ u64 pack2(float x, float y) {
    u64 r;
    asm("mov.b64 %0, {%1, %2};" : "=l"(r) : "f"(x), "f"(y));
    return r;
}
__device__ __forceinline__ void fma2(u64& d, u64 a, u64 b) {
    asm("fma.rn.f32x2 %0, %1, %2, %0;" : "+l"(d) : "l"(a), "l"(b));
}
__device__ __forceinline__ float2 unpack2(u64 v) {
    float2 u;
    asm("mov.b64 {%0, %1}, %2;" : "=f"(u.x), "=f"(u.y) : "l"(v));
    return u;
}

// polynomial exp on the FMA pipe (valid for x in (-85, 85)); rel err ~1e-7
__device__ __forceinline__ float fast_exp(float x) {
    float t = x * 1.4426950408889634f;      // x * log2(e)
    float z = t + 12582912.0f;              // round-to-nearest via magic
    int   n = __float_as_int(z) - 0x4B400000;
    float r = z - 12582912.0f;
    float f = t - r;                        // f in [-0.5, 0.5]
    float p =        1.5403530e-4f;
    p = fmaf(p, f,   1.3333558e-3f);
    p = fmaf(p, f,   9.6181291e-3f);
    p = fmaf(p, f,   5.5504109e-2f);
    p = fmaf(p, f,   2.4022651e-1f);
    p = fmaf(p, f,   6.9314718e-1f);
    p = fmaf(p, f,   1.0f);
    return __int_as_float((n + 127) << 23) * p;
}

__device__ __forceinline__ float mishf(float v) {
    float sp = (v > 20.0f) ? v : log1pf(fast_exp(fmaxf(v, -80.0f)));
    return v * tanhf(sp);
}

// 128x128x32 tile compute, 256 threads, 8x8 micro-tile, packed f32x2 FMA
__device__ __forceinline__ void mm_tile(const float* As, const float* Bs,
                                        int tm8, int tn8, u64 acc[8][4]) {
#pragma unroll
    for (int kk = 0; kk < 32; ++kk) {
        float a[8], b[8];
        *(float4*)&a[0] = *(const float4*)(As + kk * PAD + tm8);
        *(float4*)&a[4] = *(const float4*)(As + kk * PAD + tm8 + 4);
        *(float4*)&b[0] = *(const float4*)(Bs + kk * PAD + tn8);
        *(float4*)&b[4] = *(const float4*)(Bs + kk * PAD + tn8 + 4);
        u64 bp[4];
#pragma unroll
        for (int n = 0; n < 4; ++n) bp[n] = pack2(b[2 * n], b[2 * n + 1]);
#pragma unroll
        for (int m = 0; m < 8; ++m) {
            u64 ap = pack2(a[m], a[m]);
#pragma unroll
            for (int n = 0; n < 4; ++n) fma2(acc[m][n], ap, bp[n]);
        }
    }
}

__device__ __forceinline__ void unpack_acc(const u64 acc[8][4], float o[8][8]) {
#pragma unroll
    for (int m = 0; m < 8; ++m)
#pragma unroll
        for (int n = 0; n < 4; ++n) {
            float2 u = unpack2(acc[m][n]);
            o[m][2 * n]     = u.x;
            o[m][2 * n + 1] = u.y;
        }
}

#define ZERO_ACC(acc) \
    _Pragma("unroll") for (int _m = 0; _m < 8; ++_m) \
    _Pragma("unroll") for (int _n = 0; _n < 4; ++_n) acc[_m][_n] = 0ull;

// ---------------- K1: Q & K projection (+bias +PE) ----------------
// grid (32 iblk, 4 b); rows 0..63 -> Q, rows 64..127 -> K
__global__ __launch_bounds__(256) void k_proj_qk(
    const float* __restrict__ x, const float* __restrict__ WQ, const float* __restrict__ bQ,
    const float* __restrict__ WK, const float* __restrict__ bK, const float* __restrict__ PE)
{
    __shared__ __align__(16) float As[32 * PAD];
    __shared__ __align__(16) float Bs[32 * PAD];
    const int tid = threadIdx.x;
    const int i0  = blockIdx.x * 128;
    const int b   = blockIdx.y;
    const int tm8 = (tid >> 4) << 3, tn8 = (tid & 15) << 3;
    u64 acc[8][4]; ZERO_ACC(acc);

    for (int c0 = 0; c0 < CDIM; c0 += 32) {
#pragma unroll
        for (int it = 0; it < 16; ++it) {
            int idx = tid + it * 256;
            int kk = idx & 31, m = idx >> 5;
            const float* Wp = (m < QKD) ? (WQ + m * CDIM) : (WK + (m - QKD) * CDIM);
            As[kk * PAD + m] = Wp[c0 + kk];
        }
#pragma unroll
        for (int it = 0; it < 16; ++it) {
            int idx = tid + it * 256;
            int n = idx & 127, kk = idx >> 7;
            Bs[kk * PAD + n] = x[((size_t)b * CDIM + c0 + kk) * NTOK + i0 + n];
        }
        __syncthreads();
        mm_tile(As, Bs, tm8, tn8, acc);
        __syncthreads();
    }
    float o[8][8]; unpack_acc(acc, o);
#pragma unroll
    for (int m = 0; m < 8; ++m) {
        int r = tm8 + m;
        bool isQ = (r < QKD);
        int rq = isQ ? r : r - QKD;
        float bb = isQ ? bQ[rq] : bK[rq];
        float* dst = (isQ ? g_q : g_k) + ((size_t)b * QKD + rq) * NTOK + i0;
        const float* pe = PE + (size_t)rq * NTOK + i0;
#pragma unroll
        for (int n = 0; n < 8; ++n) {
            int col = tn8 + n;
            dst[col] = o[m][n] + bb + pe[col];
        }
    }
}

// ---------------- K1b: V projection ----------------
// grid (32 iblk, 2 oblk, 4 b)
__global__ __launch_bounds__(256) void k_proj_v(
    const float* __restrict__ x, const float* __restrict__ WV, const float* __restrict__ bV)
{
    __shared__ __align__(16) float As[32 * PAD];
    __shared__ __align__(16) float Bs[32 * PAD];
    const int tid = threadIdx.x;
    const int i0  = blockIdx.x * 128;
    const int o0  = blockIdx.y * 128;
    const int b   = blockIdx.z;
    const int tm8 = (tid >> 4) << 3, tn8 = (tid & 15) << 3;
    u64 acc[8][4]; ZERO_ACC(acc);

    for (int c0 = 0; c0 < CDIM; c0 += 32) {
#pragma unroll
        for (int it = 0; it < 16; ++it) {
            int idx = tid + it * 256;
            int kk = idx & 31, m = idx >> 5;
            As[kk * PAD + m] = WV[(o0 + m) * CDIM + c0 + kk];
        }
#pragma unroll
        for (int it = 0; it < 16; ++it) {
            int idx = tid + it * 256;
            int n = idx & 127, kk = idx >> 7;
            Bs[kk * PAD + n] = x[((size_t)b * CDIM + c0 + kk) * NTOK + i0 + n];
        }
        __syncthreads();
        mm_tile(As, Bs, tm8, tn8, acc);
        __syncthreads();
    }
    float o[8][8]; unpack_acc(acc, o);
#pragma unroll
    for (int m = 0; m < 8; ++m) {
        int r = o0 + tm8 + m;
        float bb = bV[r];
        float* dst = g_v + ((size_t)b * CDIM + r) * NTOK + i0 + tn8;
        float4 s0 = make_float4(o[m][0] + bb, o[m][1] + bb, o[m][2] + bb, o[m][3] + bb);
        float4 s1 = make_float4(o[m][4] + bb, o[m][5] + bb, o[m][6] + bb, o[m][7] + bb);
        *(float4*)(dst)     = s0;
        *(float4*)(dst + 4) = s1;
    }
}

// ---------------- K2: S = (Q^T K) / 8 ----------------
// grid (32 jblk, 32 iblk, 4 b)
__global__ __launch_bounds__(256) void k_qkt()
{
    __shared__ __align__(16) float As[32 * PAD];
    __shared__ __align__(16) float Bs[32 * PAD];
    const int tid = threadIdx.x;
    const int j0  = blockIdx.x * 128;
    const int i0  = blockIdx.y * 128;
    const int b   = blockIdx.z;
    const int tm8 = (tid >> 4) << 3, tn8 = (tid & 15) << 3;
    u64 acc[8][4]; ZERO_ACC(acc);

    for (int c0 = 0; c0 < QKD; c0 += 32) {
#pragma unroll
        for (int it = 0; it < 16; ++it) {
            int idx = tid + it * 256;
            int m = idx & 127, kk = idx >> 7;
            As[kk * PAD + m] = g_q[((size_t)b * QKD + c0 + kk) * NTOK + i0 + m];
        }
#pragma unroll
        for (int it = 0; it < 16; ++it) {
            int idx = tid + it * 256;
            int n = idx & 127, kk = idx >> 7;
            Bs[kk * PAD + n] = g_k[((size_t)b * QKD + c0 + kk) * NTOK + j0 + n];
        }
        __syncthreads();
        mm_tile(As, Bs, tm8, tn8, acc);
        __syncthreads();
    }
    float o[8][8]; unpack_acc(acc, o);
#pragma unroll
    for (int m = 0; m < 8; ++m) {
        size_t row = ((size_t)b * NTOK + i0 + tm8 + m) * NTOK + j0 + tn8;
        float4 s0 = make_float4(o[m][0] * 0.125f, o[m][1] * 0.125f, o[m][2] * 0.125f, o[m][3] * 0.125f);
        float4 s1 = make_float4(o[m][4] * 0.125f, o[m][5] * 0.125f, o[m][6] * 0.125f, o[m][7] * 0.125f);
        *(float4*)(g_S + row)     = s0;
        *(float4*)(g_S + row + 4) = s1;
    }
}

// ---------------- K3: E = exp(S) in place + partial column sums ----------------
// grid (16 jblk, 8 ichunk, 4 b); softmax(axis=query) == exp(S)/colsum(exp(S))
__global__ __launch_bounds__(256) void k_expsum()
{
    int j  = blockIdx.x * 256 + threadIdx.x;
    int ic = blockIdx.y;
    int b  = blockIdx.z;
    size_t base = (size_t)b * NTOK * NTOK + (size_t)ic * 512 * NTOK + j;
    float s = 0.0f;
#pragma unroll 4
    for (int i = 0; i < 512; ++i) {
        float e = fast_exp(g_S[base]);
        g_S[base] = e;
        s += e;
        base += NTOK;
    }
    g_Dp[(b * 8 + ic) * NTOK + j] = s;
}

// ---------------- K3c: w[j] = 1 / colsum ----------------
__global__ __launch_bounds__(256) void k_wcalc()
{
    int idx = blockIdx.x * 256 + threadIdx.x;     // 0 .. NB*NTOK-1
    int b = idx >> 12, j = idx & (NTOK - 1);
    float s = 0.0f;
#pragma unroll
    for (int c = 0; c < 8; ++c) s += g_Dp[(b * 8 + c) * NTOK + j];
    g_w[idx] = 1.0f / s;
}

// ---------------- K3b: fold w into V (in place; V is fully rewritten each launch) ----------------
__global__ __launch_bounds__(256) void k_scalev()
{
    size_t idx = (size_t)blockIdx.x * 256 + threadIdx.x;   // over NB*CDIM*NTOK
    int j  = (int)(idx & (NTOK - 1));
    int b  = (int)((idx >> 12) >> 8);
    g_v[idx] *= g_w[(b << 12) + j];
}

// ---------------- K4: AO = E @ V_scaled ----------------
// grid (2 cblk, 32 iblk, 4 b)
__global__ __launch_bounds__(256) void k_av()
{
    __shared__ __align__(16) float As[32 * PAD];
    __shared__ __align__(16) float Bs[32 * PAD];
    const int tid = threadIdx.x;
    const int c0  = blockIdx.x * 128;
    const int i0  = blockIdx.y * 128;
    const int b   = blockIdx.z;
    const int tm8 = (tid >> 4) << 3, tn8 = (tid & 15) << 3;
    u64 acc[8][4]; ZERO_ACC(acc);

    for (int k0 = 0; k0 < NTOK; k0 += 32) {
#pragma unroll
        for (int it = 0; it < 16; ++it) {
            int idx = tid + it * 256;
            int kk = idx & 31, m = idx >> 5;
            As[kk * PAD + m] = g_S[((size_t)b * NTOK + i0 + m) * NTOK + k0 + kk];
        }
#pragma unroll
        for (int it = 0; it < 16; ++it) {
            int idx = tid + it * 256;
            int kk = idx & 31, n = idx >> 5;
            Bs[kk * PAD + n] = g_v[((size_t)b * CDIM + c0 + n) * NTOK + k0 + kk];
        }
        __syncthreads();
        mm_tile(As, Bs, tm8, tn8, acc);
        __syncthreads();
    }
    float o[8][8]; unpack_acc(acc, o);
#pragma unroll
    for (int m = 0; m < 8; ++m) {
        size_t row = ((size_t)b * NTOK + i0 + tm8 + m) * CDIM + c0 + tn8;
        *(float4*)(g_ao + row)     = make_float4(o[m][0], o[m][1], o[m][2], o[m][3]);
        *(float4*)(g_ao + row + 4) = make_float4(o[m][4], o[m][5], o[m][6], o[m][7]);
    }
}

// ---------------- K5a: H = mish(W1 @ AO^T + b1) ----------------
// grid (32 iblk, 2 oblk, 4 b)
__global__ __launch_bounds__(256) void k_mlp1(
    const float* __restrict__ W1, const float* __restrict__ b1)
{
    __shared__ __align__(16) float As[32 * PAD];
    __shared__ __align__(16) float Bs[32 * PAD];
    const int tid = threadIdx.x;
    const int i0  = blockIdx.x * 128;
    const int o0  = blockIdx.y * 128;
    const int b   = blockIdx.z;
    const int tm8 = (tid >> 4) << 3, tn8 = (tid & 15) << 3;
    u64 acc[8][4]; ZERO_ACC(acc);

    for (int c0 = 0; c0 < CDIM; c0 += 32) {
#pragma unroll
        for (int it = 0; it < 16; ++it) {
            int idx = tid + it * 256;
            int kk = idx & 31, m = idx >> 5;
            As[kk * PAD + m] = W1[(o0 + m) * CDIM + c0 + kk];
        }
#pragma unroll
        for (int it = 0; it < 16; ++it) {
            int idx = tid + it * 256;
            int kk = idx & 31, n = idx >> 5;
            Bs[kk * PAD + n] = g_ao[((size_t)b * NTOK + i0 + n) * CDIM + c0 + kk];
        }
        __syncthreads();
        mm_tile(As, Bs, tm8, tn8, acc);
        __syncthreads();
    }
    float o[8][8]; unpack_acc(acc, o);
#pragma unroll
    for (int m = 0; m < 8; ++m) {
        int r = o0 + tm8 + m;
        float bb = b1[r];
        float* dst = g_h + ((size_t)b * CDIM + r) * NTOK + i0 + tn8;
#pragma unroll
        for (int n = 0; n < 8; ++n) dst[n] = mishf(o[m][n] + bb);
    }
}

// ---------------- K5b: OUT = W2 @ H + b2 + x ----------------
// grid (32 iblk, 2 oblk, 4 b)
__global__ __launch_bounds__(256) void k_mlp2(
    const float* __restrict__ W2, const float* __restrict__ b2,
    const float* __restrict__ x, float* __restrict__ out)
{
    __shared__ __align__(16) float As[32 * PAD];
    __shared__ __align__(16) float Bs[32 * PAD];
    const int tid = threadIdx.x;
    const int i0  = blockIdx.x * 128;
    const int o0  = blockIdx.y * 128;
    const int b   = blockIdx.z;
    const int tm8 = (tid >> 4) << 3, tn8 = (tid & 15) << 3;
    u64 acc[8][4]; ZERO_ACC(acc);

    for (int c0 = 0; c0 < CDIM; c0 += 32) {
#pragma unroll
        for (int it = 0; it < 16; ++it) {
            int idx = tid + it * 256;
            int kk = idx & 31, m = idx >> 5;
            As[kk * PAD + m] = W2[(o0 + m) * CDIM + c0 + kk];
        }
#pragma unroll
        for (int it = 0; it < 16; ++it) {
            int idx = tid + it * 256;
            int n = idx & 127, kk = idx >> 7;
            Bs[kk * PAD + n] = g_h[((size_t)b * CDIM + c0 + kk) * NTOK + i0 + n];
        }
        __syncthreads();
        mm_tile(As, Bs, tm8, tn8, acc);
        __syncthreads();
    }
    float o[8][8]; unpack_acc(acc, o);
#pragma unroll
    for (int m = 0; m < 8; ++m) {
        int r = o0 + tm8 + m;
        float bb = b2[r];
        size_t row = ((size_t)b * CDIM + r) * NTOK + i0 + tn8;
#pragma unroll
        for (int n = 0; n < 8; ++n) out[row + n] = o[m][n] + bb + x[row + n];
    }
}

// ---------------- launch ----------------
extern "C" void kernel_launch(void* const* d_in, const int* in_sizes, int n_in,
                              void* d_out, int out_size)
{
    (void)in_sizes; (void)n_in; (void)out_size;
    const float* x  = (const float*)d_in[0];
    const float* WQ = (const float*)d_in[1];
    const float* bQ = (const float*)d_in[2];
    const float* WK = (const float*)d_in[3];
    const float* bK = (const float*)d_in[4];
    const float* WV = (const float*)d_in[5];
    const float* bV = (const float*)d_in[6];
    const float* PE = (const float*)d_in[7];
    const float* W1 = (const float*)d_in[8];
    const float* b1 = (const float*)d_in[9];
    const float* W2 = (const float*)d_in[10];
    const float* b2 = (const float*)d_in[11];
    float* out = (float*)d_out;

    k_proj_qk<<<dim3(32, NB),        256>>>(x, WQ, bQ, WK, bK, PE);
    k_proj_v <<<dim3(32, 2, NB),     256>>>(x, WV, bV);
    k_qkt    <<<dim3(32, 32, NB),    256>>>();
    k_expsum <<<dim3(16, 8, NB),     256>>>();
    k_wcalc  <<<dim3(64),            256>>>();
    k_scalev <<<dim3(16384),         256>>>();
    k_av     <<<dim3(2, 32, NB),     256>>>();
    k_mlp1   <<<dim3(32, 2, NB),     256>>>(W1, b1);
    k_mlp2   <<<dim3(32, 2, NB),     256>>>(W2, b2, x, out);
}

// round 3
// speedup vs baseline: 3.9369x; 3.9369x over previous
#include <cuda_runtime.h>
#include <cuda_bf16.h>
#include <math.h>
#include <cstdint>

#define NTOK 4096
#define CDIM 256
#define QKD  64
#define NB   4
#define PAD  132

typedef unsigned long long u64;

// ---------------- scratch (device globals; no runtime allocation) ----------------
__device__ __align__(256) __nv_bfloat16 g_qb [(size_t)NB * NTOK * QKD];   // [b][i][d]
__device__ __align__(256) __nv_bfloat16 g_kb [(size_t)NB * NTOK * QKD];   // [b][j][d]
__device__ __align__(256) __nv_bfloat16 g_E  [(size_t)NB * NTOK * NTOK];  // [b][i][j] = exp(S)
__device__ __align__(256) float         g_v  [(size_t)NB * CDIM * NTOK];  // [b][c][j] fp32
__device__ __align__(256) __nv_bfloat16 g_vb [(size_t)NB * CDIM * NTOK];  // [b][c][j] bf16 * w[j]
__device__ __align__(256) float         g_Dp [NB * 8 * NTOK];
__device__ __align__(256) float         g_w  [NB * NTOK];
__device__ __align__(256) __nv_bfloat16 g_aob[(size_t)NB * NTOK * CDIM];  // [b][i][c]
__device__ __align__(256) __nv_bfloat16 g_hb [(size_t)NB * NTOK * CDIM];  // [b][i][o]
__device__ __align__(256) __nv_bfloat16 g_W1b[CDIM * CDIM];               // [o][c]
__device__ __align__(256) __nv_bfloat16 g_W2b[CDIM * CDIM];               // [o2][o]

// ---------------- PTX helpers (baseline ISA only) ----------------
__device__ __forceinline__ uint32_t smem_u32(const void* p) {
    uint32_t a;
    asm("{ .reg .u64 t; cvta.to.shared.u64 t, %1; cvt.u32.u64 %0, t; }" : "=r"(a) : "l"(p));
    return a;
}
#define CP_COMMIT()  asm volatile("cp.async.commit_group;" ::: "memory")
#define CP_WAIT2()   asm volatile("cp.async.wait_group 2;" :: : "memory")

__device__ __forceinline__ void cp16(uint32_t d, const void* s) {
    asm volatile("cp.async.cg.shared.global [%0], [%1], 16;" :: "r"(d), "l"(s) : "memory");
}
__device__ __forceinline__ void ldsm4(uint32_t r[4], uint32_t a) {
    asm volatile("ldmatrix.sync.aligned.m8n8.x4.shared.b16 {%0,%1,%2,%3}, [%4];"
                 : "=r"(r[0]), "=r"(r[1]), "=r"(r[2]), "=r"(r[3]) : "r"(a));
}
__device__ __forceinline__ void mma_bf16(float c[4], const uint32_t a[4], const uint32_t b[2]) {
    asm volatile("mma.sync.aligned.m16n8k16.row.col.f32.bf16.bf16.f32 "
                 "{%0,%1,%2,%3}, {%4,%5,%6,%7}, {%8,%9}, {%0,%1,%2,%3};"
                 : "+f"(c[0]), "+f"(c[1]), "+f"(c[2]), "+f"(c[3])
                 : "r"(a[0]), "r"(a[1]), "r"(a[2]), "r"(a[3]), "r"(b[0]), "r"(b[1]));
}
__device__ __forceinline__ uint32_t bf2(float x, float y) {
    __nv_bfloat162 h = __floats2bfloat162_rn(x, y);
    return *(uint32_t*)&h;
}

// ---------------- math helpers ----------------
__device__ __forceinline__ float fast_exp(float x) {
    float t = x * 1.4426950408889634f;
    float z = t + 12582912.0f;
    int   n = __float_as_int(z) - 0x4B400000;
    float r = z - 12582912.0f;
    float f = t - r;
    float p =        1.5403530e-4f;
    p = fmaf(p, f,   1.3333558e-3f);
    p = fmaf(p, f,   9.6181291e-3f);
    p = fmaf(p, f,   5.5504109e-2f);
    p = fmaf(p, f,   2.4022651e-1f);
    p = fmaf(p, f,   6.9314718e-1f);
    p = fmaf(p, f,   1.0f);
    return __int_as_float((n + 127) << 23) * p;
}
__device__ __forceinline__ float mishf(float v) {
    float sp = (v > 20.0f) ? v : log1pf(fast_exp(fmaxf(v, -80.0f)));
    return v * tanhf(sp);
}

// ---------------- f32x2 SIMT helpers (projections) ----------------
__device__ __forceinline__ u64 pack2(float x, float y) {
    u64 r; asm("mov.b64 %0, {%1, %2};" : "=l"(r) : "f"(x), "f"(y)); return r;
}
__device__ __forceinline__ void fma2(u64& d, u64 a, u64 b) {
    asm("fma.rn.f32x2 %0, %1, %2, %0;" : "+l"(d) : "l"(a), "l"(b));
}
__device__ __forceinline__ float2 unpack2(u64 v) {
    float2 u; asm("mov.b64 {%0, %1}, %2;" : "=f"(u.x), "=f"(u.y) : "l"(v)); return u;
}
__device__ __forceinline__ void mm_tile(const float* As, const float* Bs,
                                        int tm8, int tn8, u64 acc[8][4]) {
#pragma unroll
    for (int kk = 0; kk < 32; ++kk) {
        float a[8], b[8];
        *(float4*)&a[0] = *(const float4*)(As + kk * PAD + tm8);
        *(float4*)&a[4] = *(const float4*)(As + kk * PAD + tm8 + 4);
        *(float4*)&b[0] = *(const float4*)(Bs + kk * PAD + tn8);
        *(float4*)&b[4] = *(const float4*)(Bs + kk * PAD + tn8 + 4);
        u64 bp[4];
#pragma unroll
        for (int n = 0; n < 4; ++n) bp[n] = pack2(b[2 * n], b[2 * n + 1]);
#pragma unroll
        for (int m = 0; m < 8; ++m) {
            u64 ap = pack2(a[m], a[m]);
#pragma unroll
            for (int n = 0; n < 4; ++n) fma2(acc[m][n], ap, bp[n]);
        }
    }
}
__device__ __forceinline__ void unpack_acc(const u64 acc[8][4], float o[8][8]) {
#pragma unroll
    for (int m = 0; m < 8; ++m)
#pragma unroll
        for (int n = 0; n < 4; ++n) {
            float2 u = unpack2(acc[m][n]);
            o[m][2 * n] = u.x; o[m][2 * n + 1] = u.y;
        }
}
#define ZERO_ACC(acc) \
    _Pragma("unroll") for (int _m = 0; _m < 8; ++_m) \
    _Pragma("unroll") for (int _n = 0; _n < 4; ++_n) acc[_m][_n] = 0ull;

// ================= shared warp-MMA GEMM mainloop =================
// CTA: 256 thr (8 warps, 4 M x 2 N), tile 128(M) x 128(N), K-chunk 32 bf16.
// smem row: 64B data + 16B pad = 80B. Stage = (128 A rows + 128 B rows) * 80B.
#define ROWB   80
#define SBOFF  (128 * ROWB)
#define STG    (2 * 128 * ROWB)
#define GEMM_SMEM (4 * STG)

template <int NCH>
__device__ __forceinline__ void gemm_main(const char* __restrict__ gA, size_t lda,
                                          const char* __restrict__ gB, size_t ldb,
                                          char* smem, float acc[2][8][4])
{
    const int tid  = threadIdx.x;
    const int lane = tid & 31, wid = tid >> 5;
    const int wr = wid & 3, wc = wid >> 2;
    const uint32_t sb = smem_u32(smem);

    const int r0  = tid >> 2;       // loader row (0..63), +64 for second half
    const int seg = tid & 3;        // 16B segment within 64B row

    const uint32_t aOff = (uint32_t)((wr * 32 + (lane & 15)) * ROWB + (lane >> 4) * 16);
    const uint32_t bOff = (uint32_t)(SBOFF + (wc * 64 + (lane & 7)) * ROWB + ((lane >> 3) & 3) * 16);

#pragma unroll
    for (int s = 0; s < 3; ++s) {
        if (s < NCH) {
            uint32_t base = sb + s * STG;
#pragma unroll
            for (int h = 0; h < 2; ++h) {
                int row = r0 + h * 64;
                cp16(base + row * ROWB + seg * 16, gA + (size_t)row * lda + (size_t)s * 64 + seg * 16);
                cp16(base + SBOFF + row * ROWB + seg * 16, gB + (size_t)row * ldb + (size_t)s * 64 + seg * 16);
            }
        }
        CP_COMMIT();
    }

    for (int c = 0; c < NCH; ++c) {
        CP_WAIT2();
        __syncthreads();
        const uint32_t st = sb + (c & 3) * STG;
        uint32_t af[2][2][4], bf[8][4];
#pragma unroll
        for (int mt = 0; mt < 2; ++mt)
#pragma unroll
            for (int ks = 0; ks < 2; ++ks)
                ldsm4(af[mt][ks], st + aOff + mt * (16 * ROWB) + ks * 32);
#pragma unroll
        for (int nt = 0; nt < 8; ++nt)
            ldsm4(bf[nt], st + bOff + nt * (8 * ROWB));
#pragma unroll
        for (int ks = 0; ks < 2; ++ks)
#pragma unroll
            for (int mt = 0; mt < 2; ++mt)
#pragma unroll
                for (int nt = 0; nt < 8; ++nt)
                    mma_bf16(acc[mt][nt], af[mt][ks], &bf[nt][ks * 2]);
        __syncthreads();
        if (c + 3 < NCH) {
            uint32_t base = sb + ((c + 3) & 3) * STG;
#pragma unroll
            for (int h = 0; h < 2; ++h) {
                int row = r0 + h * 64;
                cp16(base + row * ROWB + seg * 16, gA + (size_t)row * lda + (size_t)(c + 3) * 64 + seg * 16);
                cp16(base + SBOFF + row * ROWB + seg * 16, gB + (size_t)row * ldb + (size_t)(c + 3) * 64 + seg * 16);
            }
        }
        CP_COMMIT();
    }
}

#define ACC_DECL  float acc[2][8][4]; \
    _Pragma("unroll") for (int _m = 0; _m < 2; ++_m) \
    _Pragma("unroll") for (int _n = 0; _n < 8; ++_n) \
    _Pragma("unroll") for (int _q = 0; _q < 4; ++_q) acc[_m][_n][_q] = 0.0f;

// epilogue index helpers (per thread)
#define EPI_COORDS \
    const int lane = threadIdx.x & 31, wid = threadIdx.x >> 5; \
    const int wr = wid & 3, wc = wid >> 2; \
    const int rowL = wr * 32 + (lane >> 2); \
    const int colL = wc * 64 + (lane & 3) * 2;

// ---------------- K0: weight conversion fp32 -> bf16 ----------------
__global__ __launch_bounds__(256) void k_wconv(const float* __restrict__ W1,
                                               const float* __restrict__ W2)
{
    int i = (blockIdx.x * 256 + threadIdx.x) * 4;
    float4 a = *(const float4*)(W1 + i);
    float4 b = *(const float4*)(W2 + i);
    *(uint32_t*)(g_W1b + i)     = bf2(a.x, a.y);
    *(uint32_t*)(g_W1b + i + 2) = bf2(a.z, a.w);
    *(uint32_t*)(g_W2b + i)     = bf2(b.x, b.y);
    *(uint32_t*)(g_W2b + i + 2) = bf2(b.z, b.w);
}

// ---------------- K1: Q & K projection (f32x2 SIMT) -> bf16 [i][d] ----------------
__global__ __launch_bounds__(256) void k_proj_qk(
    const float* __restrict__ x, const float* __restrict__ WQ, const float* __restrict__ bQ,
    const float* __restrict__ WK, const float* __restrict__ bK, const float* __restrict__ PE)
{
    __shared__ __align__(16) float As[32 * PAD];
    __shared__ __align__(16) float Bs[32 * PAD];
    const int tid = threadIdx.x;
    const int i0  = blockIdx.x * 128;
    const int b   = blockIdx.y;
    const int tm8 = (tid >> 4) << 3, tn8 = (tid & 15) << 3;
    u64 acc[8][4]; ZERO_ACC(acc);

    for (int c0 = 0; c0 < CDIM; c0 += 32) {
#pragma unroll
        for (int it = 0; it < 16; ++it) {
            int idx = tid + it * 256;
            int kk = idx & 31, m = idx >> 5;
            const float* Wp = (m < QKD) ? (WQ + m * CDIM) : (WK + (m - QKD) * CDIM);
            As[kk * PAD + m] = Wp[c0 + kk];
        }
#pragma unroll
        for (int it = 0; it < 16; ++it) {
            int idx = tid + it * 256;
            int n = idx & 127, kk = idx >> 7;
            Bs[kk * PAD + n] = x[((size_t)b * CDIM + c0 + kk) * NTOK + i0 + n];
        }
        __syncthreads();
        mm_tile(As, Bs, tm8, tn8, acc);
        __syncthreads();
    }
    float o[8][8]; unpack_acc(acc, o);
    bool isQ = (tm8 < QKD);
    int rq0 = isQ ? tm8 : tm8 - QKD;
    __nv_bfloat16* base = (isQ ? g_qb : g_kb) + (size_t)b * NTOK * QKD;
    float bb[8];
#pragma unroll
    for (int m = 0; m < 8; ++m) bb[m] = isQ ? bQ[rq0 + m] : bK[rq0 + m];
#pragma unroll
    for (int n = 0; n < 8; ++n) {
        int tok = i0 + tn8 + n;
        uint32_t w[4];
#pragma unroll
        for (int m2 = 0; m2 < 4; ++m2) {
            float v0 = o[2*m2][n]   + bb[2*m2]   + PE[(size_t)(rq0 + 2*m2)   * NTOK + tok];
            float v1 = o[2*m2+1][n] + bb[2*m2+1] + PE[(size_t)(rq0 + 2*m2+1) * NTOK + tok];
            w[m2] = bf2(v0, v1);
        }
        *(uint4*)(base + (size_t)tok * QKD + rq0) = make_uint4(w[0], w[1], w[2], w[3]);
    }
}

// ---------------- K1b: V projection (f32x2 SIMT, fp32 [c][j]) ----------------
__global__ __launch_bounds__(256) void k_proj_v(
    const float* __restrict__ x, const float* __restrict__ WV, const float* __restrict__ bV)
{
    __shared__ __align__(16) float As[32 * PAD];
    __shared__ __align__(16) float Bs[32 * PAD];
    const int tid = threadIdx.x;
    const int i0  = blockIdx.x * 128;
    const int o0  = blockIdx.y * 128;
    const int b   = blockIdx.z;
    const int tm8 = (tid >> 4) << 3, tn8 = (tid & 15) << 3;
    u64 acc[8][4]; ZERO_ACC(acc);

    for (int c0 = 0; c0 < CDIM; c0 += 32) {
#pragma unroll
        for (int it = 0; it < 16; ++it) {
            int idx = tid + it * 256;
            int kk = idx & 31, m = idx >> 5;
            As[kk * PAD + m] = WV[(o0 + m) * CDIM + c0 + kk];
        }
#pragma unroll
        for (int it = 0; it < 16; ++it) {
            int idx = tid + it * 256;
            int n = idx & 127, kk = idx >> 7;
            Bs[kk * PAD + n] = x[((size_t)b * CDIM + c0 + kk) * NTOK + i0 + n];
        }
        __syncthreads();
        mm_tile(As, Bs, tm8, tn8, acc);
        __syncthreads();
    }
    float o[8][8]; unpack_acc(acc, o);
#pragma unroll
    for (int m = 0; m < 8; ++m) {
        int r = o0 + tm8 + m;
        float bb = bV[r];
        float* dst = g_v + ((size_t)b * CDIM + r) * NTOK + i0 + tn8;
        *(float4*)(dst)     = make_float4(o[m][0] + bb, o[m][1] + bb, o[m][2] + bb, o[m][3] + bb);
        *(float4*)(dst + 4) = make_float4(o[m][4] + bb, o[m][5] + bb, o[m][6] + bb, o[m][7] + bb);
    }
}

// ---------------- K2: QK^T mma + fused exp -> bf16 E ----------------
// grid (32 j, 32 i, 4 b)
__global__ __launch_bounds__(256) void k_qkt_w()
{
    extern __shared__ char smem[];
    const int j0 = blockIdx.x * 128, i0 = blockIdx.y * 128, b = blockIdx.z;
    ACC_DECL;
    gemm_main<2>((const char*)(g_qb + ((size_t)b * NTOK + i0) * QKD), 128,
                 (const char*)(g_kb + ((size_t)b * NTOK + j0) * QKD), 128,
                 smem, acc);
    EPI_COORDS;
#pragma unroll
    for (int mt = 0; mt < 2; ++mt)
#pragma unroll
        for (int nt = 0; nt < 8; ++nt) {
            int col = j0 + colL + nt * 8;
#pragma unroll
            for (int h = 0; h < 2; ++h) {
                int row = i0 + rowL + mt * 16 + h * 8;
                uint32_t w = bf2(fast_exp(acc[mt][nt][h*2]   * 0.125f),
                                 fast_exp(acc[mt][nt][h*2+1] * 0.125f));
                *(uint32_t*)(g_E + ((size_t)b * NTOK + row) * NTOK + col) = w;
            }
        }
}

// ---------------- K3: column partial sums of E ----------------
__global__ __launch_bounds__(256) void k_colsum()
{
    int j2 = blockIdx.x * 256 + threadIdx.x;
    int ic = blockIdx.y, b = blockIdx.z;
    const __nv_bfloat162* p = (const __nv_bfloat162*)g_E
        + (size_t)(b * NTOK + ic * 512) * (NTOK / 2) + j2;
    float sx = 0.0f, sy = 0.0f;
#pragma unroll 8
    for (int i = 0; i < 512; ++i) {
        __nv_bfloat162 v = p[(size_t)i * (NTOK / 2)];
        sx += __bfloat162float(v.x);
        sy += __bfloat162float(v.y);
    }
    ((float2*)g_Dp)[(size_t)(b * 8 + ic) * (NTOK / 2) + j2] = make_float2(sx, sy);
}

// ---------------- K3b: w = 1/colsum ----------------
__global__ __launch_bounds__(256) void k_wcalc()
{
    int idx = blockIdx.x * 256 + threadIdx.x;
    int b = idx >> 12, j = idx & (NTOK - 1);
    float s = 0.0f;
#pragma unroll
    for (int c = 0; c < 8; ++c) s += g_Dp[(b * 8 + c) * NTOK + j];
    g_w[idx] = 1.0f / s;
}

// ---------------- K3c: Vb = bf16(V * w[j]) ----------------
__global__ __launch_bounds__(256) void k_scalev()
{
    size_t e4 = ((size_t)blockIdx.x * 256 + threadIdx.x) * 4;
    int j = (int)(e4 & (NTOK - 1));
    int b = (int)(e4 >> 20);
    float4 v = *(const float4*)(g_v + e4);
    float4 w = *(const float4*)(g_w + (b << 12) + j);
    *(uint32_t*)(g_vb + e4)     = bf2(v.x * w.x, v.y * w.y);
    *(uint32_t*)(g_vb + e4 + 2) = bf2(v.z * w.z, v.w * w.w);
}

// ---------------- K4: AO = E @ Vb (mma) -> bf16 ao[i][c] ----------------
// grid (2 cblk, 32 iblk, 4 b)
__global__ __launch_bounds__(256) void k_av_w()
{
    extern __shared__ char smem[];
    const int n0 = blockIdx.x * 128, i0 = blockIdx.y * 128, b = blockIdx.z;
    ACC_DECL;
    gemm_main<128>((const char*)(g_E  + ((size_t)b * NTOK + i0) * NTOK), 8192,
                   (const char*)(g_vb + ((size_t)b * CDIM + n0) * NTOK), 8192,
                   smem, acc);
    EPI_COORDS;
#pragma unroll
    for (int mt = 0; mt < 2; ++mt)
#pragma unroll
        for (int nt = 0; nt < 8; ++nt) {
            int col = n0 + colL + nt * 8;
#pragma unroll
            for (int h = 0; h < 2; ++h) {
                int row = i0 + rowL + mt * 16 + h * 8;
                *(uint32_t*)(g_aob + ((size_t)b * NTOK + row) * CDIM + col)
                    = bf2(acc[mt][nt][h*2], acc[mt][nt][h*2+1]);
            }
        }
}

// ---------------- K5a: H = mish(AO @ W1^T + b1) -> bf16 h[i][o] ----------------
// grid (2 oblk, 32 iblk, 4 b); M=i, N=o, K=c
__global__ __launch_bounds__(256) void k_mlp1_w(const float* __restrict__ b1)
{
    extern __shared__ char smem[];
    const int n0 = blockIdx.x * 128, i0 = blockIdx.y * 128, b = blockIdx.z;
    ACC_DECL;
    gemm_main<8>((const char*)(g_aob + ((size_t)b * NTOK + i0) * CDIM), 512,
                 (const char*)(g_W1b + (size_t)n0 * CDIM), 512,
                 smem, acc);
    EPI_COORDS;
#pragma unroll
    for (int nt = 0; nt < 8; ++nt) {
        int col = n0 + colL + nt * 8;
        float bb0 = b1[col], bb1 = b1[col + 1];
#pragma unroll
        for (int mt = 0; mt < 2; ++mt)
#pragma unroll
            for (int h = 0; h < 2; ++h) {
                int row = i0 + rowL + mt * 16 + h * 8;
                *(uint32_t*)(g_hb + ((size_t)b * NTOK + row) * CDIM + col)
                    = bf2(mishf(acc[mt][nt][h*2] + bb0), mishf(acc[mt][nt][h*2+1] + bb1));
            }
    }
}

// ---------------- K5b: OUT = W2 @ H^T + b2 + x (mma) ----------------
// grid (32 iblk, 2 cblk, 4 b); M=c, N=i, K=o
__global__ __launch_bounds__(256) void k_mlp2_w(
    const float* __restrict__ b2, const float* __restrict__ x, float* __restrict__ out)
{
    extern __shared__ char smem[];
    const int n0 = blockIdx.x * 128, m0 = blockIdx.y * 128, b = blockIdx.z;
    ACC_DECL;
    gemm_main<8>((const char*)(g_W2b + (size_t)m0 * CDIM), 512,
                 (const char*)(g_hb + ((size_t)b * NTOK + n0) * CDIM), 512,
                 smem, acc);
    EPI_COORDS;
#pragma unroll
    for (int mt = 0; mt < 2; ++mt)
#pragma unroll
        for (int h = 0; h < 2; ++h) {
            int row = m0 + rowL + mt * 16 + h * 8;
            float bb = b2[row];
            size_t base = ((size_t)b * CDIM + row) * NTOK;
#pragma unroll
            for (int nt = 0; nt < 8; ++nt) {
                int col = n0 + colL + nt * 8;
                float2 xv = *(const float2*)(x + base + col);
                float2 ov = make_float2(acc[mt][nt][h*2]   + bb + xv.x,
                                        acc[mt][nt][h*2+1] + bb + xv.y);
                *(float2*)(out + base + col) = ov;
            }
        }
}

// ---------------- launch ----------------
extern "C" void kernel_launch(void* const* d_in, const int* in_sizes, int n_in,
                              void* d_out, int out_size)
{
    (void)in_sizes; (void)n_in; (void)out_size;
    const float* x  = (const float*)d_in[0];
    const float* WQ = (const float*)d_in[1];
    const float* bQ = (const float*)d_in[2];
    const float* WK = (const float*)d_in[3];
    const float* bK = (const float*)d_in[4];
    const float* WV = (const float*)d_in[5];
    const float* bV = (const float*)d_in[6];
    const float* PE = (const float*)d_in[7];
    const float* W1 = (const float*)d_in[8];
    const float* b1 = (const float*)d_in[9];
    const float* W2 = (const float*)d_in[10];
    const float* b2 = (const float*)d_in[11];
    float* out = (float*)d_out;

    cudaFuncSetAttribute(k_qkt_w,  cudaFuncAttributeMaxDynamicSharedMemorySize, GEMM_SMEM);
    cudaFuncSetAttribute(k_av_w,   cudaFuncAttributeMaxDynamicSharedMemorySize, GEMM_SMEM);
    cudaFuncSetAttribute(k_mlp1_w, cudaFuncAttributeMaxDynamicSharedMemorySize, GEMM_SMEM);
    cudaFuncSetAttribute(k_mlp2_w, cudaFuncAttributeMaxDynamicSharedMemorySize, GEMM_SMEM);

    k_wconv  <<<dim3(64),         256>>>(W1, W2);
    k_proj_qk<<<dim3(32, NB),     256>>>(x, WQ, bQ, WK, bK, PE);
    k_proj_v <<<dim3(32, 2, NB),  256>>>(x, WV, bV);
    k_qkt_w  <<<dim3(32, 32, NB), 256, GEMM_SMEM>>>();
    k_colsum <<<dim3(8, 8, NB),   256>>>();
    k_wcalc  <<<dim3(64),         256>>>();
    k_scalev <<<dim3(4096),       256>>>();
    k_av_w   <<<dim3(2, 32, NB),  256, GEMM_SMEM>>>();
    k_mlp1_w <<<dim3(2, 32, NB),  256, GEMM_SMEM>>>(b1);
    k_mlp2_w <<<dim3(32, 2, NB),  256, GEMM_SMEM>>>(b2, x, out);
}

// round 4
// speedup vs baseline: 5.7489x; 1.4603x over previous
#include <cuda_runtime.h>
#include <cuda_bf16.h>
#include <math.h>
#include <cstdint>

#define NTOK 4096
#define CDIM 256
#define QKD  64
#define NB   4

typedef unsigned long long u64;

// ---------------- scratch (device globals) ----------------
__device__ __align__(256) __nv_bfloat16 g_xt  [(size_t)NB * NTOK * CDIM];  // [b][j][c] bf16
__device__ __align__(256) float         g_pet [(size_t)NTOK * QKD];        // PE^T [i][d] fp32
__device__ __align__(256) __nv_bfloat16 g_qb  [(size_t)NB * NTOK * QKD];   // [b][i][d]
__device__ __align__(256) __nv_bfloat16 g_kb  [(size_t)NB * NTOK * QKD];   // [b][j][d]
__device__ __align__(256) __nv_bfloat16 g_E   [(size_t)NB * NTOK * NTOK];  // [b][i][j] = exp(S)
__device__ __align__(256) __nv_bfloat16 g_vb  [(size_t)NB * CDIM * NTOK];  // [b][c][j] bf16 * w[j]
__device__ __align__(256) float         g_cs  [NB * NTOK];                 // column sums (atomic)
__device__ __align__(256) float         g_w   [NB * NTOK];                 // 1 / colsum
__device__ __align__(256) __nv_bfloat16 g_aob [(size_t)NB * NTOK * CDIM];  // [b][i][c]
__device__ __align__(256) __nv_bfloat16 g_hb  [(size_t)NB * NTOK * CDIM];  // [b][i][o]
__device__ __align__(256) __nv_bfloat16 g_W1b [CDIM * CDIM];               // [o][c]
__device__ __align__(256) __nv_bfloat16 g_W2b [CDIM * CDIM];               // [o2][o]
__device__ __align__(256) __nv_bfloat16 g_WVb [CDIM * CDIM];               // [c][c']
__device__ __align__(256) __nv_bfloat16 g_WQKb[2 * QKD * CDIM];            // [dq|dk][c']

// ---------------- PTX helpers (baseline ISA only) ----------------
__device__ __forceinline__ uint32_t smem_u32(const void* p) {
    uint32_t a;
    asm("{ .reg .u64 t; cvta.to.shared.u64 t, %1; cvt.u32.u64 %0, t; }" : "=r"(a) : "l"(p));
    return a;
}
#define CP_COMMIT()  asm volatile("cp.async.commit_group;" ::: "memory")
template <int N>
__device__ __forceinline__ void cp_wait() {
    asm volatile("cp.async.wait_group %0;" :: "n"(N) : "memory");
}
__device__ __forceinline__ void cp16(uint32_t d, const void* s) {
    asm volatile("cp.async.cg.shared.global [%0], [%1], 16;" :: "r"(d), "l"(s) : "memory");
}
__device__ __forceinline__ void ldsm4(uint32_t r[4], uint32_t a) {
    asm volatile("ldmatrix.sync.aligned.m8n8.x4.shared.b16 {%0,%1,%2,%3}, [%4];"
                 : "=r"(r[0]), "=r"(r[1]), "=r"(r[2]), "=r"(r[3]) : "r"(a));
}
__device__ __forceinline__ void mma_bf16(float c[4], const uint32_t a[4], const uint32_t b[2]) {
    asm volatile("mma.sync.aligned.m16n8k16.row.col.f32.bf16.bf16.f32 "
                 "{%0,%1,%2,%3}, {%4,%5,%6,%7}, {%8,%9}, {%0,%1,%2,%3};"
                 : "+f"(c[0]), "+f"(c[1]), "+f"(c[2]), "+f"(c[3])
                 : "r"(a[0]), "r"(a[1]), "r"(a[2]), "r"(a[3]), "r"(b[0]), "r"(b[1]));
}
__device__ __forceinline__ uint32_t bf2(float x, float y) {
    __nv_bfloat162 h = __floats2bfloat162_rn(x, y);
    return *(uint32_t*)&h;
}
__device__ __forceinline__ float ex2f(float x) {
    float y; asm("ex2.approx.f32 %0, %1;" : "=f"(y) : "f"(x)); return y;
}
__device__ __forceinline__ float lg2f_a(float x) {
    float y; asm("lg2.approx.f32 %0, %1;" : "=f"(y) : "f"(x)); return y;
}
__device__ __forceinline__ float tanh_a(float x) {
    float y; asm("tanh.approx.f32 %0, %1;" : "=f"(y) : "f"(x)); return y;
}
// mish on MUFU: v * tanh(ln(1 + e^v))
__device__ __forceinline__ float mishf(float v) {
    float t  = ex2f(v * 1.4426950408889634f);
    float sp = lg2f_a(1.0f + t) * 0.6931471805599453f;
    return v * tanh_a(sp);
}
#define QK_SCL 0.18033688011112042f   /* 0.125 * log2(e) */

// ================= shared warp-MMA GEMM mainloop =================
// CTA: 256 thr (8 warps, 4 M x 2 N), tile 128(M) x 128(N), K-chunk 32 bf16 (64B).
#define ROWB   80
#define SBOFF  (128 * ROWB)
#define STG    (2 * 128 * ROWB)
#define SMEM4  (4 * STG)
#define SMEM2  (2 * STG)

template <int NCH, int NST>
__device__ __forceinline__ void gemm_main(const char* __restrict__ gA, size_t lda,
                                          const char* __restrict__ gB, size_t ldb,
                                          char* smem, float acc[2][8][4])
{
    const int tid  = threadIdx.x;
    const int lane = tid & 31, wid = tid >> 5;
    const int wr = wid & 3, wc = wid >> 2;
    const uint32_t sb = smem_u32(smem);

    const int r0  = tid >> 2;
    const int seg = tid & 3;

    const uint32_t aOff = (uint32_t)((wr * 32 + (lane & 15)) * ROWB + (lane >> 4) * 16);
    const uint32_t bOff = (uint32_t)(SBOFF + (wc * 64 + (lane & 7)) * ROWB + ((lane >> 3) & 3) * 16);

#pragma unroll
    for (int s = 0; s < NST - 1; ++s) {
        if (s < NCH) {
            uint32_t base = sb + s * STG;
#pragma unroll
            for (int h = 0; h < 2; ++h) {
                int row = r0 + h * 64;
                cp16(base + row * ROWB + seg * 16, gA + (size_t)row * lda + (size_t)s * 64 + seg * 16);
                cp16(base + SBOFF + row * ROWB + seg * 16, gB + (size_t)row * ldb + (size_t)s * 64 + seg * 16);
            }
        }
        CP_COMMIT();
    }

    for (int c = 0; c < NCH; ++c) {
        cp_wait<NST - 2>();
        __syncthreads();
        const uint32_t st = sb + (c % NST) * STG;
        uint32_t af[2][2][4], bf[8][4];
#pragma unroll
        for (int mt = 0; mt < 2; ++mt)
#pragma unroll
            for (int ks = 0; ks < 2; ++ks)
                ldsm4(af[mt][ks], st + aOff + mt * (16 * ROWB) + ks * 32);
#pragma unroll
        for (int nt = 0; nt < 8; ++nt)
            ldsm4(bf[nt], st + bOff + nt * (8 * ROWB));
#pragma unroll
        for (int ks = 0; ks < 2; ++ks)
#pragma unroll
            for (int mt = 0; mt < 2; ++mt)
#pragma unroll
                for (int nt = 0; nt < 8; ++nt)
                    mma_bf16(acc[mt][nt], af[mt][ks], &bf[nt][ks * 2]);
        __syncthreads();
        if (c + NST - 1 < NCH) {
            uint32_t base = sb + ((c + NST - 1) % NST) * STG;
#pragma unroll
            for (int h = 0; h < 2; ++h) {
                int row = r0 + h * 64;
                cp16(base + row * ROWB + seg * 16, gA + (size_t)row * lda + (size_t)(c + NST - 1) * 64 + seg * 16);
                cp16(base + SBOFF + row * ROWB + seg * 16, gB + (size_t)row * ldb + (size_t)(c + NST - 1) * 64 + seg * 16);
            }
        }
        CP_COMMIT();
    }
}

#define ACC_DECL  float acc[2][8][4]; \
    _Pragma("unroll") for (int _m = 0; _m < 2; ++_m) \
    _Pragma("unroll") for (int _n = 0; _n < 8; ++_n) \
    _Pragma("unroll") for (int _q = 0; _q < 4; ++_q) acc[_m][_n][_q] = 0.0f;

#define EPI_COORDS \
    const int lane = threadIdx.x & 31, wid = threadIdx.x >> 5; \
    const int wr = wid & 3, wc = wid >> 2; \
    const int rowL = wr * 32 + (lane >> 2); \
    const int colL = wc * 64 + (lane & 3) * 2; \
    (void)wr; (void)wc;

// ---------------- K0: prep — weight conversions + zero colsum ----------------
__device__ __forceinline__ void conv4(const float* s, __nv_bfloat16* d, int i) {
    float4 v = *(const float4*)(s + i);
    *(uint32_t*)(d + i)     = bf2(v.x, v.y);
    *(uint32_t*)(d + i + 2) = bf2(v.z, v.w);
}
__global__ __launch_bounds__(256) void k_prep(
    const float* __restrict__ W1, const float* __restrict__ W2, const float* __restrict__ WV,
    const float* __restrict__ WQ, const float* __restrict__ WK)
{
    int blk = blockIdx.x, t = threadIdx.x;
    if (blk < 16) {
        int base = blk * 4096;
#pragma unroll
        for (int p = 0; p < 4; ++p) conv4(W1, g_W1b, base + p * 1024 + t * 4);
    } else if (blk < 32) {
        int base = (blk - 16) * 4096;
#pragma unroll
        for (int p = 0; p < 4; ++p) conv4(W2, g_W2b, base + p * 1024 + t * 4);
    } else if (blk < 48) {
        int base = (blk - 32) * 4096;
#pragma unroll
        for (int p = 0; p < 4; ++p) conv4(WV, g_WVb, base + p * 1024 + t * 4);
    } else if (blk < 56) {
        int base = (blk - 48) * 4096;
#pragma unroll
        for (int p = 0; p < 4; ++p) {
            int i = base + p * 1024 + t * 4;
            const float* s = (i < QKD * CDIM) ? (WQ + i) : (WK + i - QKD * CDIM);
            float4 v = *(const float4*)s;
            *(uint32_t*)(g_WQKb + i)     = bf2(v.x, v.y);
            *(uint32_t*)(g_WQKb + i + 2) = bf2(v.z, v.w);
        }
    } else {
        int base = (blk - 56) * 4096;
#pragma unroll
        for (int p = 0; p < 4; ++p)
            *(float4*)(g_cs + base + p * 1024 + t * 4) = make_float4(0.f, 0.f, 0.f, 0.f);
    }
}

// ---------------- K0b: x [b][c][j] fp32 -> x_t [b][j][c] bf16 ----------------
// grid (32 jt, 8 ct, 4 b): tile 32c x 128j
__global__ __launch_bounds__(256) void k_xt(const float* __restrict__ x)
{
    __shared__ float ts[32][129];
    const int jt = blockIdx.x * 128, ct = blockIdx.y * 32, b = blockIdx.z;
    const int tid = threadIdx.x;
#pragma unroll
    for (int p = 0; p < 4; ++p) {
        int c = (tid >> 5) + p * 8;
        int j = (tid & 31) * 4;
        float4 v = *(const float4*)(x + ((size_t)b * CDIM + ct + c) * NTOK + jt + j);
        ts[c][j] = v.x; ts[c][j+1] = v.y; ts[c][j+2] = v.z; ts[c][j+3] = v.w;
    }
    __syncthreads();
#pragma unroll
    for (int p = 0; p < 8; ++p) {
        int idx = tid + p * 256;          // 0..2047
        int j = idx >> 4, cp = idx & 15;
        *(uint32_t*)(g_xt + ((size_t)b * NTOK + jt + j) * CDIM + ct + cp * 2)
            = bf2(ts[cp * 2][j], ts[cp * 2 + 1][j]);
    }
}

// ---------------- K0c: PE [d][i] -> PEt [i][d] fp32 ----------------
// grid (128 it, 2 dt)
__global__ __launch_bounds__(256) void k_pet(const float* __restrict__ PE)
{
    __shared__ float ts[32][33];
    const int it = blockIdx.x * 32, dt = blockIdx.y * 32;
    const int r = threadIdx.x >> 5, c = threadIdx.x & 31;
#pragma unroll
    for (int p = 0; p < 4; ++p)
        ts[r + p * 8][c] = PE[(size_t)(dt + r + p * 8) * NTOK + it + c];
    __syncthreads();
#pragma unroll
    for (int p = 0; p < 4; ++p)
        g_pet[(size_t)(it + r + p * 8) * QKD + dt + c] = ts[c][r + p * 8];
}

// ---------------- K1: QK projection (mma): C[i][dq|dk] + bias + PEt -> g_qb/g_kb ----------------
// grid (32 iblk, 4 b)
__global__ __launch_bounds__(256) void k_projqk_w(
    const float* __restrict__ bQ, const float* __restrict__ bK)
{
    extern __shared__ char smem[];
    const int i0 = blockIdx.x * 128, b = blockIdx.y;
    ACC_DECL;
    gemm_main<8, 4>((const char*)(g_xt + ((size_t)b * NTOK + i0) * CDIM), 512,
                    (const char*)g_WQKb, 512, smem, acc);
    EPI_COORDS;
    const bool isQ = (wc == 0);
    __nv_bfloat16* dst = (isQ ? g_qb : g_kb) + (size_t)b * NTOK * QKD;
#pragma unroll
    for (int nt = 0; nt < 8; ++nt) {
        int d = (lane & 3) * 2 + nt * 8;             // 0..63
        float b0 = isQ ? bQ[d]     : bK[d];
        float b1 = isQ ? bQ[d + 1] : bK[d + 1];
#pragma unroll
        for (int mt = 0; mt < 2; ++mt)
#pragma unroll
            for (int h = 0; h < 2; ++h) {
                int row = i0 + rowL + mt * 16 + h * 8;
                float2 pe = *(const float2*)(g_pet + (size_t)row * QKD + d);
                *(uint32_t*)(dst + (size_t)row * QKD + d)
                    = bf2(acc[mt][nt][h*2] + b0 + pe.x, acc[mt][nt][h*2+1] + b1 + pe.y);
            }
    }
}

// ---------------- K2: QK^T mma + MUFU exp -> bf16 E + fused column sums ----------------
// grid (32 j, 32 i, 4 b)
__global__ __launch_bounds__(256) void k_qkt_w()
{
    extern __shared__ char smem[];
    const int j0 = blockIdx.x * 128, i0 = blockIdx.y * 128, b = blockIdx.z;
    ACC_DECL;
    gemm_main<2, 2>((const char*)(g_qb + ((size_t)b * NTOK + i0) * QKD), 128,
                    (const char*)(g_kb + ((size_t)b * NTOK + j0) * QKD), 128,
                    smem, acc);
    EPI_COORDS;
    float cs[8][2];
#pragma unroll
    for (int nt = 0; nt < 8; ++nt) { cs[nt][0] = 0.f; cs[nt][1] = 0.f; }
#pragma unroll
    for (int mt = 0; mt < 2; ++mt)
#pragma unroll
        for (int nt = 0; nt < 8; ++nt) {
            int col = j0 + colL + nt * 8;
#pragma unroll
            for (int h = 0; h < 2; ++h) {
                int row = i0 + rowL + mt * 16 + h * 8;
                float e0 = ex2f(acc[mt][nt][h*2]   * QK_SCL);
                float e1 = ex2f(acc[mt][nt][h*2+1] * QK_SCL);
                __nv_bfloat162 hh = __floats2bfloat162_rn(e0, e1);
                *(uint32_t*)(g_E + ((size_t)b * NTOK + row) * NTOK + col) = *(uint32_t*)&hh;
                cs[nt][0] += __bfloat162float(hh.x);   // sum of ROUNDED values
                cs[nt][1] += __bfloat162float(hh.y);
            }
        }
    // reduce over the 8 row-lanes (lane>>2) within each warp
#pragma unroll
    for (int nt = 0; nt < 8; ++nt)
#pragma unroll
        for (int p = 0; p < 2; ++p) {
            float v = cs[nt][p];
            v += __shfl_xor_sync(0xFFFFFFFFu, v, 4);
            v += __shfl_xor_sync(0xFFFFFFFFu, v, 8);
            v += __shfl_xor_sync(0xFFFFFFFFu, v, 16);
            cs[nt][p] = v;
        }
    float* sred = (float*)smem;
    if (threadIdx.x < 128) sred[threadIdx.x] = 0.0f;
    __syncthreads();
    if ((lane >> 2) == 0) {
#pragma unroll
        for (int nt = 0; nt < 8; ++nt) {
            int cc = wc * 64 + (lane & 3) * 2 + nt * 8;
            atomicAdd(&sred[cc],     cs[nt][0]);
            atomicAdd(&sred[cc + 1], cs[nt][1]);
        }
    }
    __syncthreads();
    if (threadIdx.x < 128)
        atomicAdd(&g_cs[(size_t)b * NTOK + j0 + threadIdx.x], sred[threadIdx.x]);
}

// ---------------- K2b: w = 1/colsum ----------------
__global__ __launch_bounds__(256) void k_wcalc()
{
    int idx = blockIdx.x * 256 + threadIdx.x;
    g_w[idx] = 1.0f / g_cs[idx];
}

// ---------------- K3: V projection (mma): C[c][j] = WV @ x, epilogue *w[j]+bias -> g_vb ----------------
// grid (32 jblk, 2 mblk, 4 b)
__global__ __launch_bounds__(256) void k_projv_w(const float* __restrict__ bV)
{
    extern __shared__ char smem[];
    const int j0 = blockIdx.x * 128, m0 = blockIdx.y * 128, b = blockIdx.z;
    ACC_DECL;
    gemm_main<8, 4>((const char*)(g_WVb + (size_t)m0 * CDIM), 512,
                    (const char*)(g_xt + ((size_t)b * NTOK + j0) * CDIM), 512,
                    smem, acc);
    EPI_COORDS;
#pragma unroll
    for (int mt = 0; mt < 2; ++mt)
#pragma unroll
        for (int h = 0; h < 2; ++h) {
            int row = m0 + rowL + mt * 16 + h * 8;
            float bb = bV[row];
#pragma unroll
            for (int nt = 0; nt < 8; ++nt) {
                int col = j0 + colL + nt * 8;
                float2 w2 = *(const float2*)(g_w + (size_t)b * NTOK + col);
                *(uint32_t*)(g_vb + ((size_t)b * CDIM + row) * NTOK + col)
                    = bf2((acc[mt][nt][h*2] + bb) * w2.x, (acc[mt][nt][h*2+1] + bb) * w2.y);
            }
        }
}

// ---------------- K4: AO = E @ Vb -> bf16 ao[i][c] ----------------
// grid (2 cblk, 32 iblk, 4 b)
__global__ __launch_bounds__(256) void k_av_w()
{
    extern __shared__ char smem[];
    const int n0 = blockIdx.x * 128, i0 = blockIdx.y * 128, b = blockIdx.z;
    ACC_DECL;
    gemm_main<128, 4>((const char*)(g_E  + ((size_t)b * NTOK + i0) * NTOK), 8192,
                      (const char*)(g_vb + ((size_t)b * CDIM + n0) * NTOK), 8192,
                      smem, acc);
    EPI_COORDS;
#pragma unroll
    for (int mt = 0; mt < 2; ++mt)
#pragma unroll
        for (int nt = 0; nt < 8; ++nt) {
            int col = n0 + colL + nt * 8;
#pragma unroll
            for (int h = 0; h < 2; ++h) {
                int row = i0 + rowL + mt * 16 + h * 8;
                *(uint32_t*)(g_aob + ((size_t)b * NTOK + row) * CDIM + col)
                    = bf2(acc[mt][nt][h*2], acc[mt][nt][h*2+1]);
            }
        }
}

// ---------------- K5a: H = mish(AO @ W1^T + b1) -> bf16 h[i][o] ----------------
// grid (2 oblk, 32 iblk, 4 b)
__global__ __launch_bounds__(256) void k_mlp1_w(const float* __restrict__ b1)
{
    extern __shared__ char smem[];
    const int n0 = blockIdx.x * 128, i0 = blockIdx.y * 128, b = blockIdx.z;
    ACC_DECL;
    gemm_main<8, 4>((const char*)(g_aob + ((size_t)b * NTOK + i0) * CDIM), 512,
                    (const char*)(g_W1b + (size_t)n0 * CDIM), 512,
                    smem, acc);
    EPI_COORDS;
#pragma unroll
    for (int nt = 0; nt < 8; ++nt) {
        int col = n0 + colL + nt * 8;
        float bb0 = b1[col], bb1 = b1[col + 1];
#pragma unroll
        for (int mt = 0; mt < 2; ++mt)
#pragma unroll
            for (int h = 0; h < 2; ++h) {
                int row = i0 + rowL + mt * 16 + h * 8;
                *(uint32_t*)(g_hb + ((size_t)b * NTOK + row) * CDIM + col)
                    = bf2(mishf(acc[mt][nt][h*2] + bb0), mishf(acc[mt][nt][h*2+1] + bb1));
            }
    }
}

// ---------------- K5b: OUT = W2 @ H^T + b2 + x ----------------
// grid (32 iblk, 2 cblk, 4 b)
__global__ __launch_bounds__(256) void k_mlp2_w(
    const float* __restrict__ b2, const float* __restrict__ x, float* __restrict__ out)
{
    extern __shared__ char smem[];
    const int n0 = blockIdx.x * 128, m0 = blockIdx.y * 128, b = blockIdx.z;
    ACC_DECL;
    gemm_main<8, 4>((const char*)(g_W2b + (size_t)m0 * CDIM), 512,
                    (const char*)(g_hb + ((size_t)b * NTOK + n0) * CDIM), 512,
                    smem, acc);
    EPI_COORDS;
#pragma unroll
    for (int mt = 0; mt < 2; ++mt)
#pragma unroll
        for (int h = 0; h < 2; ++h) {
            int row = m0 + rowL + mt * 16 + h * 8;
            float bb = b2[row];
            size_t base = ((size_t)b * CDIM + row) * NTOK;
#pragma unroll
            for (int nt = 0; nt < 8; ++nt) {
                int col = n0 + colL + nt * 8;
                float2 xv = *(const float2*)(x + base + col);
                *(float2*)(out + base + col)
                    = make_float2(acc[mt][nt][h*2]   + bb + xv.x,
                                  acc[mt][nt][h*2+1] + bb + xv.y);
            }
        }
}

// ---------------- launch ----------------
extern "C" void kernel_launch(void* const* d_in, const int* in_sizes, int n_in,
                              void* d_out, int out_size)
{
    (void)in_sizes; (void)n_in; (void)out_size;
    const float* x  = (const float*)d_in[0];
    const float* WQ = (const float*)d_in[1];
    const float* bQ = (const float*)d_in[2];
    const float* WK = (const float*)d_in[3];
    const float* bK = (const float*)d_in[4];
    const float* WV = (const float*)d_in[5];
    const float* bV = (const float*)d_in[6];
    const float* PE = (const float*)d_in[7];
    const float* W1 = (const float*)d_in[8];
    const float* b1 = (const float*)d_in[9];
    const float* W2 = (const float*)d_in[10];
    const float* b2 = (const float*)d_in[11];
    float* out = (float*)d_out;

    cudaFuncSetAttribute(k_projqk_w, cudaFuncAttributeMaxDynamicSharedMemorySize, SMEM4);
    cudaFuncSetAttribute(k_qkt_w,    cudaFuncAttributeMaxDynamicSharedMemorySize, SMEM2);
    cudaFuncSetAttribute(k_projv_w,  cudaFuncAttributeMaxDynamicSharedMemorySize, SMEM4);
    cudaFuncSetAttribute(k_av_w,     cudaFuncAttributeMaxDynamicSharedMemorySize, SMEM4);
    cudaFuncSetAttribute(k_mlp1_w,   cudaFuncAttributeMaxDynamicSharedMemorySize, SMEM4);
    cudaFuncSetAttribute(k_mlp2_w,   cudaFuncAttributeMaxDynamicSharedMemorySize, SMEM4);

    k_prep    <<<dim3(60),          256>>>(W1, W2, WV, WQ, WK);
    k_xt      <<<dim3(32, 8, NB),   256>>>(x);
    k_pet     <<<dim3(128, 2),      256>>>(PE);
    k_projqk_w<<<dim3(32, NB),      256, SMEM4>>>(bQ, bK);
    k_qkt_w   <<<dim3(32, 32, NB),  256, SMEM2>>>();
    k_wcalc   <<<dim3(64),          256>>>();
    k_projv_w <<<dim3(32, 2, NB),   256, SMEM4>>>(bV);
    k_av_w    <<<dim3(2, 32, NB),   256, SMEM4>>>();
    k_mlp1_w  <<<dim3(2, 32, NB),   256, SMEM4>>>(b1);
    k_mlp2_w  <<<dim3(32, 2, NB),   256, SMEM4>>>(b2, x, out);
}